// round 1
// baseline (speedup 1.0000x reference)
#include <cuda_runtime.h>
#include <math.h>

// PhotonicQuantumWalk: B=8, N=2048, C=2, STEPS=64, LOSS_DB=0.1
//
// Pipeline:
//   init_kernel      : zero deg, fill state0 = 1/64
//   gemm_mask_kernel : z[b,n,k] = adj[b,n,:]·enc_w[k,:] + enc_b[k] (fp32);
//                      writes bit-packed TRANSPOSED mask maskT[b][m][n-words]
//                      and row degrees deg[b][n] (atomicAdd over k-tiles)
//   isd_kernel       : inv_sqrt_deg
//   step_kernel ×64  : coin rotation (with 1/(prev-norm+1e-8) folded in),
//                      bit-masked column sums (warp per output row, amp in smem),
//                      loss factor, deterministic partial-norm reduction
//   fc_kernel        : probs -> relu fc1 -> fc2 -> d_out (8×64)

#define BATCH  8
#define NN     2048
#define NWORDS (NN / 32)   // 64
#define STEPS  64
#define SBLK   32          // step-kernel blocks per batch (rows/block = 64)

// ---------------- device scratch (no allocation allowed) ----------------
__device__ float    g_sA[BATCH * NN * 4];          // state buffers (B,N,C,2)
__device__ float    g_sB[BATCH * NN * 4];
__device__ unsigned g_maskT[BATCH * NN * NWORDS];  // maskT[b][m][w] bits over n
__device__ int      g_deg[BATCH * NN];
__device__ float    g_isd[BATCH * NN];             // inv_sqrt_deg
__device__ float    g_partials[2][BATCH][SBLK];    // per-step ||s||^2 partials

// ---------------- init ----------------
__global__ void init_kernel() {
    int i = blockIdx.x * blockDim.x + threadIdx.x;
    if (i < BATCH * NN * 4) g_sA[i] = 0.015625f;   // 1/sqrt(N*C) = 1/64 exactly
    if (i < BATCH * NN)     g_deg[i] = 0;
}

// ---------------- enc GEMM + mask extraction ----------------
// C[n,k] = sum_m A[n,m] * W[k,m]  (both K-contiguous, "NT" gemm)
// Tile 128x128, BK=16, 256 threads, 8x8 per thread.
__global__ void __launch_bounds__(256) gemm_mask_kernel(
    const float* __restrict__ adj, const float* __restrict__ W,
    const float* __restrict__ bias) {
    __shared__ float As[16][128];
    __shared__ float Bs[16][128];
    __shared__ unsigned char sgn[128][128];

    int b  = blockIdx.z;
    int k0 = blockIdx.x * 128;
    int n0 = blockIdx.y * 128;
    const float* A = adj + (size_t)b * NN * NN;

    int tid  = threadIdx.x;
    int tx   = tid & 15;       // k sub-tile
    int ty   = tid >> 4;       // n sub-tile
    int lrow = tid >> 2;       // 0..63
    int lcol = (tid & 3) << 2; // 0,4,8,12

    float acc[8][8];
#pragma unroll
    for (int i = 0; i < 8; i++)
#pragma unroll
        for (int j = 0; j < 8; j++) acc[i][j] = 0.f;

    for (int kt = 0; kt < NN; kt += 16) {
        float4 a0 = *(const float4*)&A[(size_t)(n0 + lrow)      * NN + kt + lcol];
        float4 a1 = *(const float4*)&A[(size_t)(n0 + lrow + 64) * NN + kt + lcol];
        float4 b0 = *(const float4*)&W[(size_t)(k0 + lrow)      * NN + kt + lcol];
        float4 b1 = *(const float4*)&W[(size_t)(k0 + lrow + 64) * NN + kt + lcol];
        __syncthreads();
        As[lcol + 0][lrow] = a0.x; As[lcol + 1][lrow] = a0.y;
        As[lcol + 2][lrow] = a0.z; As[lcol + 3][lrow] = a0.w;
        As[lcol + 0][lrow + 64] = a1.x; As[lcol + 1][lrow + 64] = a1.y;
        As[lcol + 2][lrow + 64] = a1.z; As[lcol + 3][lrow + 64] = a1.w;
        Bs[lcol + 0][lrow] = b0.x; Bs[lcol + 1][lrow] = b0.y;
        Bs[lcol + 2][lrow] = b0.z; Bs[lcol + 3][lrow] = b0.w;
        Bs[lcol + 0][lrow + 64] = b1.x; Bs[lcol + 1][lrow + 64] = b1.y;
        Bs[lcol + 2][lrow + 64] = b1.z; Bs[lcol + 3][lrow + 64] = b1.w;
        __syncthreads();
#pragma unroll
        for (int kk = 0; kk < 16; kk++) {
            float av[8], bv[8];
            *(float4*)&av[0] = *(const float4*)&As[kk][ty * 8];
            *(float4*)&av[4] = *(const float4*)&As[kk][ty * 8 + 4];
            *(float4*)&bv[0] = *(const float4*)&Bs[kk][tx * 8];
            *(float4*)&bv[4] = *(const float4*)&Bs[kk][tx * 8 + 4];
#pragma unroll
            for (int i = 0; i < 8; i++)
#pragma unroll
                for (int j = 0; j < 8; j++) acc[i][j] += av[i] * bv[j];
        }
    }
    __syncthreads();

    // sign bytes (sigmoid(z) > 0.5  <=>  z > 0)
#pragma unroll
    for (int i = 0; i < 8; i++) {
#pragma unroll
        for (int j = 0; j < 8; j++) {
            float z = acc[i][j] + bias[k0 + tx * 8 + j];
            sgn[ty * 8 + i][tx * 8 + j] = (z > 0.f) ? 1 : 0;
        }
    }
    __syncthreads();

    // bit-pack transposed mask: maskT[b][k][word-of-n]
    for (int idx = tid; idx < 512; idx += 256) {
        int kl = idx >> 2;
        int w  = idx & 3;
        unsigned word = 0;
#pragma unroll
        for (int i = 0; i < 32; i++)
            word |= ((unsigned)sgn[w * 32 + i][kl]) << i;
        g_maskT[((size_t)b * NN + (k0 + kl)) * NWORDS + (n0 >> 5) + w] = word;
    }
    // row degrees: deg[b][n] += popcount over this k-tile
    if (tid < 128) {
        int s = 0;
#pragma unroll 16
        for (int j = 0; j < 128; j++) s += sgn[tid][j];
        atomicAdd(&g_deg[b * NN + n0 + tid], s);
    }
}

// ---------------- inv_sqrt_deg ----------------
__global__ void isd_kernel() {
    int i = blockIdx.x * blockDim.x + threadIdx.x;
    if (i < BATCH * NN) {
        int d = g_deg[i];
        g_isd[i] = (d > 0) ? (1.0f / sqrtf((float)d)) : 0.0f;
    }
}

// ---------------- one walk step ----------------
// state_t = s_{t-1} / (||s_{t-1}|| + 1e-8)  is folded into the coin scalar.
// grid: (SBLK, BATCH), 512 threads (16 warps), 4 output rows per warp.
__global__ void __launch_bounds__(512) step_kernel(
    const float* __restrict__ coin, int step, float lf) {
    __shared__ float4 amp[NN];          // 32 KB
    __shared__ float  warpsum[16];

    int b    = blockIdx.y;
    int tid  = threadIdx.x;
    int lane = tid & 31;
    int wid  = tid >> 5;

    const float4* s_in  = (const float4*)((step & 1) ? g_sB : g_sA);
    float4*       s_out = (float4*)((step & 1) ? g_sA : g_sB);

    // divisor from previous step's partial norms (deterministic fixed-order sum)
    float d = 1.0f;
    if (step > 0) {
        const float* p = g_partials[(step - 1) & 1][b];
        float t = 0.f;
#pragma unroll
        for (int i = 0; i < SBLK; i++) t += p[i];
        d = sqrtf(t) + 1e-8f;
    }

    // normalized coin (Frobenius) with 1/d folded in
    float c[8];
    float cn = 0.f;
#pragma unroll
    for (int i = 0; i < 8; i++) { c[i] = coin[i]; cn += c[i] * c[i]; }
    float inv = 1.0f / (sqrtf(cn) * d);
#pragma unroll
    for (int i = 0; i < 8; i++) c[i] *= inv;
    // c: [c00r c00i c01r c01i c10r c10i c11r c11i]

    // amp[n] = (coin @ cs)[n] * inv_sqrt_deg[n]   (into smem)
    for (int n = tid; n < NN; n += 512) {
        float4 s = s_in[b * NN + n];
        float e0r = c[0] * s.x - c[1] * s.y + c[2] * s.z - c[3] * s.w;
        float e0i = c[0] * s.y + c[1] * s.x + c[2] * s.w + c[3] * s.z;
        float e1r = c[4] * s.x - c[5] * s.y + c[6] * s.z - c[7] * s.w;
        float e1i = c[4] * s.y + c[5] * s.x + c[6] * s.w + c[7] * s.z;
        float f = g_isd[b * NN + n];
        amp[n] = make_float4(e0r * f, e0i * f, e1r * f, e1i * f);
    }
    __syncthreads();

    float local = 0.f;
#pragma unroll
    for (int r = 0; r < 4; r++) {
        int m = blockIdx.x * 64 + wid * 4 + r;
        const unsigned* mw = &g_maskT[((size_t)b * NN + m) * NWORDS];
        unsigned w0 = mw[lane * 2];
        unsigned w1 = mw[lane * 2 + 1];
        unsigned long long bits = ((unsigned long long)w1 << 32) | (unsigned long long)w0;
        float ax = 0.f, ay = 0.f, az = 0.f, aw = 0.f;
        int nb = lane * 64;
        while (bits) {
            int i = __ffsll((long long)bits) - 1;
            bits &= bits - 1;
            float4 a = amp[nb + i];
            ax += a.x; ay += a.y; az += a.z; aw += a.w;
        }
#pragma unroll
        for (int off = 16; off > 0; off >>= 1) {
            ax += __shfl_xor_sync(0xffffffffu, ax, off);
            ay += __shfl_xor_sync(0xffffffffu, ay, off);
            az += __shfl_xor_sync(0xffffffffu, az, off);
            aw += __shfl_xor_sync(0xffffffffu, aw, off);
        }
        if (lane == 0) {
            if (g_deg[b * NN + m] == 0) {
                // isolated node keeps its (coin-rotated, deg-unscaled) amplitude
                float4 s = s_in[b * NN + m];
                ax = c[0] * s.x - c[1] * s.y + c[2] * s.z - c[3] * s.w;
                ay = c[0] * s.y + c[1] * s.x + c[2] * s.w + c[3] * s.z;
                az = c[4] * s.x - c[5] * s.y + c[6] * s.z - c[7] * s.w;
                aw = c[4] * s.y + c[5] * s.x + c[6] * s.w + c[7] * s.z;
            }
            ax *= lf; ay *= lf; az *= lf; aw *= lf;
            s_out[b * NN + m] = make_float4(ax, ay, az, aw);
            local += ax * ax + ay * ay + az * az + aw * aw;
        }
    }
    if (lane == 0) warpsum[wid] = local;
    __syncthreads();
    if (tid == 0) {
        float t = 0.f;
#pragma unroll
        for (int i = 0; i < 16; i++) t += warpsum[i];
        g_partials[step & 1][b][blockIdx.x] = t;
    }
}

// ---------------- final probs + 2-layer MLP ----------------
__global__ void __launch_bounds__(128) fc_kernel(
    const float* __restrict__ f1w, const float* __restrict__ f1b,
    const float* __restrict__ f2w, const float* __restrict__ f2b,
    float* __restrict__ out) {
    __shared__ __align__(16) float probs[NN * 2];
    __shared__ float h[128];
    int b = blockIdx.x, tid = threadIdx.x;

    // final normalization of step-63 output (lives in g_sA, partials slot 1)
    const float* p = g_partials[(STEPS - 1) & 1][b];
    float t = 0.f;
#pragma unroll
    for (int i = 0; i < SBLK; i++) t += p[i];
    float dd = sqrtf(t) + 1e-8f;
    float sc = 1.0f / (dd * dd);

    const float4* s = (const float4*)g_sA;
    for (int n = tid; n < NN; n += 128) {
        float4 v = s[b * NN + n];
        probs[2 * n]     = (v.x * v.x + v.y * v.y) * sc;
        probs[2 * n + 1] = (v.z * v.z + v.w * v.w) * sc;
    }
    __syncthreads();

    {
        int j = tid;  // 128 hidden units
        float acc = f1b[j];
        const float4* w4 = (const float4*)(f1w + (size_t)j * NN * 2);
        const float4* p4 = (const float4*)probs;
#pragma unroll 4
        for (int i = 0; i < NN * 2 / 4; i++) {
            float4 w = w4[i];
            float4 q = p4[i];
            acc += w.x * q.x + w.y * q.y + w.z * q.z + w.w * q.w;
        }
        h[j] = fmaxf(acc, 0.f);
    }
    __syncthreads();
    if (tid < 64) {
        float acc = f2b[tid];
#pragma unroll 8
        for (int j = 0; j < 128; j++) acc += h[j] * f2w[tid * 128 + j];
        out[b * 64 + tid] = acc;
    }
}

// ---------------- launch ----------------
extern "C" void kernel_launch(void* const* d_in, const int* in_sizes, int n_in,
                              void* d_out, int out_size) {
    const float* adj  = (const float*)d_in[0];  // (8,2048,2048)
    const float* coin = (const float*)d_in[1];  // (2,2,2)
    const float* encw = (const float*)d_in[2];  // (2048,2048)
    const float* encb = (const float*)d_in[3];  // (2048,)
    const float* f1w  = (const float*)d_in[4];  // (128,4096)
    const float* f1b  = (const float*)d_in[5];  // (128,)
    const float* f2w  = (const float*)d_in[6];  // (64,128)
    const float* f2b  = (const float*)d_in[7];  // (64,)
    float* out = (float*)d_out;                 // (8,64)

    init_kernel<<<(BATCH * NN * 4 + 255) / 256, 256>>>();

    dim3 gg(NN / 128, NN / 128, BATCH);
    gemm_mask_kernel<<<gg, 256>>>(adj, encw, encb);

    isd_kernel<<<(BATCH * NN + 255) / 256, 256>>>();

    for (int t = 0; t < STEPS; t++) {
        step_kernel<<<dim3(SBLK, BATCH), 512>>>(coin, t, expf(-0.01f * (float)t));
    }

    fc_kernel<<<BATCH, 128>>>(f1w, f1b, f2w, f2b, out);
}

// round 2
// speedup vs baseline: 1.4073x; 1.4073x over previous
#include <cuda_runtime.h>
#include <math.h>

// PhotonicQuantumWalk: B=8, N=2048, C=2, STEPS=64, LOSS_DB=0.1
//
//   init_kernel      : zero deg, fill state0 = 1/64
//   gemm_mask_kernel : fp32 NT GEMM -> bit-packed transposed mask + degrees
//   isd_kernel       : inv_sqrt_deg
//   step_kernel x64  : register-tiled predicated f32x2 shift
//                      (warp = 8 rows, lane-resident amp, shfl mask bcast)
//   fc_kernel        : probs -> relu fc1 -> fc2

#define BATCH  8
#define NN     2048
#define NWORDS (NN / 32)   // 64
#define STEPS  64
#define SBLK   32          // step blocks per batch (64 rows/block)

__device__ float    g_sA[BATCH * NN * 4];
__device__ float    g_sB[BATCH * NN * 4];
__device__ unsigned g_maskT[BATCH * NN * NWORDS];  // maskT[b][m][w] bits over n
__device__ int      g_deg[BATCH * NN];
__device__ float    g_isd[BATCH * NN];
__device__ float    g_partials[2][BATCH][SBLK];

// ---------------- init ----------------
__global__ void init_kernel() {
    int i = blockIdx.x * blockDim.x + threadIdx.x;
    if (i < BATCH * NN * 4) g_sA[i] = 0.015625f;   // 1/sqrt(N*C)
    if (i < BATCH * NN)     g_deg[i] = 0;
}

// ---------------- enc GEMM + mask extraction ----------------
__global__ void __launch_bounds__(256) gemm_mask_kernel(
    const float* __restrict__ adj, const float* __restrict__ W,
    const float* __restrict__ bias) {
    __shared__ float As[16][128];
    __shared__ float Bs[16][128];
    __shared__ unsigned char sgn[128][128];

    int b  = blockIdx.z;
    int k0 = blockIdx.x * 128;
    int n0 = blockIdx.y * 128;
    const float* A = adj + (size_t)b * NN * NN;

    int tid  = threadIdx.x;
    int tx   = tid & 15;
    int ty   = tid >> 4;
    int lrow = tid >> 2;
    int lcol = (tid & 3) << 2;

    float acc[8][8];
#pragma unroll
    for (int i = 0; i < 8; i++)
#pragma unroll
        for (int j = 0; j < 8; j++) acc[i][j] = 0.f;

    for (int kt = 0; kt < NN; kt += 16) {
        float4 a0 = *(const float4*)&A[(size_t)(n0 + lrow)      * NN + kt + lcol];
        float4 a1 = *(const float4*)&A[(size_t)(n0 + lrow + 64) * NN + kt + lcol];
        float4 b0 = *(const float4*)&W[(size_t)(k0 + lrow)      * NN + kt + lcol];
        float4 b1 = *(const float4*)&W[(size_t)(k0 + lrow + 64) * NN + kt + lcol];
        __syncthreads();
        As[lcol + 0][lrow] = a0.x; As[lcol + 1][lrow] = a0.y;
        As[lcol + 2][lrow] = a0.z; As[lcol + 3][lrow] = a0.w;
        As[lcol + 0][lrow + 64] = a1.x; As[lcol + 1][lrow + 64] = a1.y;
        As[lcol + 2][lrow + 64] = a1.z; As[lcol + 3][lrow + 64] = a1.w;
        Bs[lcol + 0][lrow] = b0.x; Bs[lcol + 1][lrow] = b0.y;
        Bs[lcol + 2][lrow] = b0.z; Bs[lcol + 3][lrow] = b0.w;
        Bs[lcol + 0][lrow + 64] = b1.x; Bs[lcol + 1][lrow + 64] = b1.y;
        Bs[lcol + 2][lrow + 64] = b1.z; Bs[lcol + 3][lrow + 64] = b1.w;
        __syncthreads();
#pragma unroll
        for (int kk = 0; kk < 16; kk++) {
            float av[8], bv[8];
            *(float4*)&av[0] = *(const float4*)&As[kk][ty * 8];
            *(float4*)&av[4] = *(const float4*)&As[kk][ty * 8 + 4];
            *(float4*)&bv[0] = *(const float4*)&Bs[kk][tx * 8];
            *(float4*)&bv[4] = *(const float4*)&Bs[kk][tx * 8 + 4];
#pragma unroll
            for (int i = 0; i < 8; i++)
#pragma unroll
                for (int j = 0; j < 8; j++) acc[i][j] += av[i] * bv[j];
        }
    }
    __syncthreads();

#pragma unroll
    for (int i = 0; i < 8; i++) {
#pragma unroll
        for (int j = 0; j < 8; j++) {
            float z = acc[i][j] + bias[k0 + tx * 8 + j];
            sgn[ty * 8 + i][tx * 8 + j] = (z > 0.f) ? 1 : 0;
        }
    }
    __syncthreads();

    for (int idx = tid; idx < 512; idx += 256) {
        int kl = idx >> 2;
        int w  = idx & 3;
        unsigned word = 0;
#pragma unroll
        for (int i = 0; i < 32; i++)
            word |= ((unsigned)sgn[w * 32 + i][kl]) << i;
        g_maskT[((size_t)b * NN + (k0 + kl)) * NWORDS + (n0 >> 5) + w] = word;
    }
    if (tid < 128) {
        int s = 0;
#pragma unroll 16
        for (int j = 0; j < 128; j++) s += sgn[tid][j];
        atomicAdd(&g_deg[b * NN + n0 + tid], s);
    }
}

// ---------------- inv_sqrt_deg ----------------
__global__ void isd_kernel() {
    int i = blockIdx.x * blockDim.x + threadIdx.x;
    if (i < BATCH * NN) {
        int d = g_deg[i];
        g_isd[i] = (d > 0) ? (1.0f / sqrtf((float)d)) : 0.0f;
    }
}

// ---------------- one walk step ----------------
// Block: 256 threads = 8 warps, 8 rows/warp -> 64 rows/block, SBLK=32 blocks/batch.
// Lane-resident amp (1 LDS.128 per 32-n chunk, shared by 8 rows),
// mask words in registers, shfl broadcast, predicated packed f32x2 adds.
__global__ void __launch_bounds__(256) step_kernel(
    const float* __restrict__ coin, int step, float lf) {
    __shared__ float4 amp[NN];       // 32 KB
    __shared__ float  warpsum[8];

    int b    = blockIdx.y;
    int tid  = threadIdx.x;
    int lane = tid & 31;
    int wid  = tid >> 5;

    const float4* s_in  = (const float4*)((step & 1) ? g_sB : g_sA);
    float4*       s_out = (float4*)((step & 1) ? g_sA : g_sB);

    // divisor from previous step's partial norms (fixed-order sum)
    float d = 1.0f;
    if (step > 0) {
        const float* p = g_partials[(step - 1) & 1][b];
        float t = 0.f;
#pragma unroll
        for (int i = 0; i < SBLK; i++) t += p[i];
        d = sqrtf(t) + 1e-8f;
    }

    // Frobenius-normalized coin with 1/d folded in
    float c[8];
    float cn = 0.f;
#pragma unroll
    for (int i = 0; i < 8; i++) { c[i] = coin[i]; cn += c[i] * c[i]; }
    float inv = 1.0f / (sqrtf(cn) * d);
#pragma unroll
    for (int i = 0; i < 8; i++) c[i] *= inv;

    // amp[n] = (coin @ cs)[n] * inv_sqrt_deg[n]
    for (int n = tid; n < NN; n += 256) {
        float4 s = s_in[b * NN + n];
        float e0r = c[0] * s.x - c[1] * s.y + c[2] * s.z - c[3] * s.w;
        float e0i = c[0] * s.y + c[1] * s.x + c[2] * s.w + c[3] * s.z;
        float e1r = c[4] * s.x - c[5] * s.y + c[6] * s.z - c[7] * s.w;
        float e1i = c[4] * s.y + c[5] * s.x + c[6] * s.w + c[7] * s.z;
        float f = g_isd[b * NN + n];
        amp[n] = make_float4(e0r * f, e0i * f, e1r * f, e1i * f);
    }

    // mask words for this warp's 8 rows -> registers (lane l holds words l, l+32)
    int m0 = blockIdx.x * 64 + wid * 8;
    unsigned mw[2][8];
#pragma unroll
    for (int r = 0; r < 8; r++) {
        const unsigned* base = &g_maskT[((size_t)b * NN + m0 + r) * NWORDS];
        mw[0][r] = base[lane];
        mw[1][r] = base[32 + lane];
    }
    __syncthreads();

    unsigned long long a0[8], a1[8];
#pragma unroll
    for (int r = 0; r < 8; r++) { a0[r] = 0ull; a1[r] = 0ull; }
    unsigned lanebit = 1u << lane;

#pragma unroll
    for (int h = 0; h < 2; h++) {
#pragma unroll 4
        for (int w2 = 0; w2 < 32; w2++) {
            int n = ((h << 5) + w2) * 32 + lane;
            ulonglong2 v = *reinterpret_cast<const ulonglong2*>(&amp[n]);
#pragma unroll
            for (int r = 0; r < 8; r++) {
                unsigned word = __shfl_sync(0xffffffffu, mw[h][r], w2);
                unsigned bit = word & lanebit;
                asm volatile(
                    "{\n\t.reg .pred p;\n\t"
                    "setp.ne.u32 p, %4, 0;\n\t"
                    "@p add.rn.f32x2 %0, %0, %2;\n\t"
                    "@p add.rn.f32x2 %1, %1, %3;\n\t}"
                    : "+l"(a0[r]), "+l"(a1[r])
                    : "l"(v.x), "l"(v.y), "r"(bit));
            }
        }
    }

    // per-row warp reduction + epilogue
    float local = 0.f;
#pragma unroll
    for (int r = 0; r < 8; r++) {
        float ax = __uint_as_float((unsigned)a0[r]);
        float ay = __uint_as_float((unsigned)(a0[r] >> 32));
        float az = __uint_as_float((unsigned)a1[r]);
        float aw = __uint_as_float((unsigned)(a1[r] >> 32));
#pragma unroll
        for (int off = 16; off > 0; off >>= 1) {
            ax += __shfl_xor_sync(0xffffffffu, ax, off);
            ay += __shfl_xor_sync(0xffffffffu, ay, off);
            az += __shfl_xor_sync(0xffffffffu, az, off);
            aw += __shfl_xor_sync(0xffffffffu, aw, off);
        }
        if (lane == 0) {
            int m = m0 + r;
            if (g_deg[b * NN + m] == 0) {
                float4 s = s_in[b * NN + m];
                ax = c[0] * s.x - c[1] * s.y + c[2] * s.z - c[3] * s.w;
                ay = c[0] * s.y + c[1] * s.x + c[2] * s.w + c[3] * s.z;
                az = c[4] * s.x - c[5] * s.y + c[6] * s.z - c[7] * s.w;
                aw = c[4] * s.y + c[5] * s.x + c[6] * s.w + c[7] * s.z;
            }
            ax *= lf; ay *= lf; az *= lf; aw *= lf;
            s_out[b * NN + m] = make_float4(ax, ay, az, aw);
            local += ax * ax + ay * ay + az * az + aw * aw;
        }
    }
    if (lane == 0) warpsum[wid] = local;
    __syncthreads();
    if (tid == 0) {
        float t = 0.f;
#pragma unroll
        for (int i = 0; i < 8; i++) t += warpsum[i];
        g_partials[step & 1][b][blockIdx.x] = t;
    }
}

// ---------------- final probs + 2-layer MLP ----------------
__global__ void __launch_bounds__(128) fc_kernel(
    const float* __restrict__ f1w, const float* __restrict__ f1b,
    const float* __restrict__ f2w, const float* __restrict__ f2b,
    float* __restrict__ out) {
    __shared__ __align__(16) float probs[NN * 2];
    __shared__ float h[128];
    int b = blockIdx.x, tid = threadIdx.x;

    const float* p = g_partials[(STEPS - 1) & 1][b];
    float t = 0.f;
#pragma unroll
    for (int i = 0; i < SBLK; i++) t += p[i];
    float dd = sqrtf(t) + 1e-8f;
    float sc = 1.0f / (dd * dd);

    const float4* s = (const float4*)g_sA;
    for (int n = tid; n < NN; n += 128) {
        float4 v = s[b * NN + n];
        probs[2 * n]     = (v.x * v.x + v.y * v.y) * sc;
        probs[2 * n + 1] = (v.z * v.z + v.w * v.w) * sc;
    }
    __syncthreads();

    {
        int j = tid;
        float acc = f1b[j];
        const float4* w4 = (const float4*)(f1w + (size_t)j * NN * 2);
        const float4* p4 = (const float4*)probs;
#pragma unroll 4
        for (int i = 0; i < NN * 2 / 4; i++) {
            float4 w = w4[i];
            float4 q = p4[i];
            acc += w.x * q.x + w.y * q.y + w.z * q.z + w.w * q.w;
        }
        h[j] = fmaxf(acc, 0.f);
    }
    __syncthreads();
    if (tid < 64) {
        float acc = f2b[tid];
#pragma unroll 8
        for (int j = 0; j < 128; j++) acc += h[j] * f2w[tid * 128 + j];
        out[b * 64 + tid] = acc;
    }
}

// ---------------- launch ----------------
extern "C" void kernel_launch(void* const* d_in, const int* in_sizes, int n_in,
                              void* d_out, int out_size) {
    const float* adj  = (const float*)d_in[0];
    const float* coin = (const float*)d_in[1];
    const float* encw = (const float*)d_in[2];
    const float* encb = (const float*)d_in[3];
    const float* f1w  = (const float*)d_in[4];
    const float* f1b  = (const float*)d_in[5];
    const float* f2w  = (const float*)d_in[6];
    const float* f2b  = (const float*)d_in[7];
    float* out = (float*)d_out;

    init_kernel<<<(BATCH * NN * 4 + 255) / 256, 256>>>();

    dim3 gg(NN / 128, NN / 128, BATCH);
    gemm_mask_kernel<<<gg, 256>>>(adj, encw, encb);

    isd_kernel<<<(BATCH * NN + 255) / 256, 256>>>();

    for (int t = 0; t < STEPS; t++) {
        step_kernel<<<dim3(SBLK, BATCH), 256>>>(coin, t, expf(-0.01f * (float)t));
    }

    fc_kernel<<<BATCH, 128>>>(f1w, f1b, f2w, f2b, out);
}

// round 4
// speedup vs baseline: 2.6056x; 1.8515x over previous
#include <cuda_runtime.h>
#include <cuda_bf16.h>
#include <math.h>
#include <stdint.h>

// PhotonicQuantumWalk: B=8, N=2048, C=2, STEPS=64, LOSS_DB=0.1
// sm_100 baseline ISA only (no tcgen05): HMMA mma.sync + ldmatrix + cp.async.
//
//   conv_split       : fp32 -> exact bf16 hi/lo split (adj, enc_w)
//   gemm_mask_mma    : bf16 3-product HMMA GEMM -> bit-packed maskT + deg
//   isd_kernel       : inv_sqrt_deg
//   step_kernel x64  : register-tiled predicated f32x2 shift (512 thr)
//   fc_kernel        : probs -> relu fc1 -> fc2

#define BATCH  8
#define NN     2048
#define NWORDS (NN / 32)
#define STEPS  64
#define SBLK   32

// ---------------- device scratch ----------------
__device__ float    g_sA[BATCH * NN * 4];
__device__ float    g_sB[BATCH * NN * 4];
__device__ unsigned g_maskT[BATCH * NN * NWORDS];
__device__ int      g_deg[BATCH * NN];
__device__ float    g_isd[BATCH * NN];
__device__ float    g_partials[2][BATCH][SBLK];
__device__ __nv_bfloat16 g_adj_hi[(size_t)BATCH * NN * NN];
__device__ __nv_bfloat16 g_adj_lo[(size_t)BATCH * NN * NN];
__device__ __nv_bfloat16 g_w_hi[(size_t)NN * NN];
__device__ __nv_bfloat16 g_w_lo[(size_t)NN * NN];

// ---------------- helpers ----------------
__device__ __forceinline__ uint32_t smem_u32(const void* p) {
    uint32_t a;
    asm("{ .reg .u64 t; cvta.to.shared.u64 t, %1; cvt.u32.u64 %0, t; }"
        : "=r"(a) : "l"(p));
    return a;
}

#define LDM4(r, addr) \
    asm volatile("ldmatrix.sync.aligned.m8n8.x4.shared.b16 {%0,%1,%2,%3}, [%4];" \
        : "=r"((r)[0]), "=r"((r)[1]), "=r"((r)[2]), "=r"((r)[3]) : "r"(addr))

#define MMA16816(d, a, b0, b1) \
    asm volatile("mma.sync.aligned.m16n8k16.row.col.f32.bf16.bf16.f32 " \
        "{%0,%1,%2,%3}, {%4,%5,%6,%7}, {%8,%9}, {%0,%1,%2,%3};" \
        : "+f"((d)[0]), "+f"((d)[1]), "+f"((d)[2]), "+f"((d)[3]) \
        : "r"((a)[0]), "r"((a)[1]), "r"((a)[2]), "r"((a)[3]), "r"(b0), "r"(b1))

#define CP_ASYNC16(dst, src) \
    asm volatile("cp.async.cg.shared.global [%0], [%1], 16;" :: "r"(dst), "l"(src))
#define CP_COMMIT() asm volatile("cp.async.commit_group;" ::: "memory")
#define CP_WAIT(n)  asm volatile("cp.async.wait_group %0;" :: "n"(n) : "memory")

// ---------------- init ----------------
__global__ void init_kernel() {
    int i = blockIdx.x * blockDim.x + threadIdx.x;
    if (i < BATCH * NN * 4) g_sA[i] = 0.015625f;   // 1/sqrt(N*C)
    if (i < BATCH * NN)     g_deg[i] = 0;
}

// ---------------- fp32 -> bf16 hi/lo split ----------------
__global__ void conv_split_kernel(const float* __restrict__ src,
                                  __nv_bfloat16* __restrict__ hi,
                                  __nv_bfloat16* __restrict__ lo, size_t n4) {
    size_t i = (size_t)blockIdx.x * blockDim.x + threadIdx.x;
    if (i >= n4) return;
    float4 v = ((const float4*)src)[i];
    __nv_bfloat16 h0 = __float2bfloat16(v.x);
    __nv_bfloat16 h1 = __float2bfloat16(v.y);
    __nv_bfloat16 h2 = __float2bfloat16(v.z);
    __nv_bfloat16 h3 = __float2bfloat16(v.w);
    __nv_bfloat16 l0 = __float2bfloat16(v.x - __bfloat162float(h0));
    __nv_bfloat16 l1 = __float2bfloat16(v.y - __bfloat162float(h1));
    __nv_bfloat16 l2 = __float2bfloat16(v.z - __bfloat162float(h2));
    __nv_bfloat16 l3 = __float2bfloat16(v.w - __bfloat162float(h3));
    __nv_bfloat162* H = (__nv_bfloat162*)hi;
    __nv_bfloat162* L = (__nv_bfloat162*)lo;
    H[2 * i]     = __nv_bfloat162(h0, h1);
    H[2 * i + 1] = __nv_bfloat162(h2, h3);
    L[2 * i]     = __nv_bfloat162(l0, l1);
    L[2 * i + 1] = __nv_bfloat162(l2, l3);
}

// ---------------- HMMA GEMM + mask extraction ----------------
// z[n,j] = sum_m adj[b,n,m] * w[j,m]  via Ah*Wh + Ah*Wl + Al*Wh (bf16, fp32 acc).
// CTA tile 128(n) x 128(j), BK=32, 3-stage cp.async pipeline.
// smem stage: [Ah | Al | Wh | Wl], each 128 rows x 64B, XOR-swizzled:
//   off(row, c16) = row*64 + ((c16 ^ ((row>>1)&3)) << 4)
#define BK       32
#define GCHUNKS  (NN / BK)     // 64
#define TILE_B   8192          // 128 * 64B
#define STAGE_B  (4 * TILE_B)  // 32 KB
#define GSTAGES  3

#define LOAD_CHUNK(cc, stg) do {                                               \
    uint32_t dstb = smb + (stg) * STAGE_B;                                     \
    int kt = (cc) * BK;                                                        \
    _Pragma("unroll")                                                          \
    for (int it = 0; it < 8; it++) {                                           \
        int arr = it >> 1;                                                     \
        int rem = ((it & 1) << 8) + tid;                                       \
        int row = rem >> 2;                                                    \
        int ch  = rem & 3;                                                     \
        int gr  = ((arr < 2) ? n0 : j0) + row;                                 \
        const __nv_bfloat16* src = srcs[arr] + (size_t)gr * NN + kt + ch * 8;  \
        uint32_t dst = dstb + arr * TILE_B + row * 64 +                        \
                       (((ch ^ ((row >> 1) & 3))) << 4);                       \
        CP_ASYNC16(dst, src);                                                  \
    }                                                                          \
    CP_COMMIT();                                                               \
} while (0)

__global__ void __launch_bounds__(256, 2) gemm_mask_mma(const float* __restrict__ bias) {
    extern __shared__ __align__(1024) char sm[];
    __shared__ float sbias[128];

    int tid  = threadIdx.x;
    int lane = tid & 31;
    int wid  = tid >> 5;
    int b  = blockIdx.z;
    int j0 = blockIdx.x * 128;
    int n0 = blockIdx.y * 128;

    const __nv_bfloat16* srcs[4] = {
        g_adj_hi + (size_t)b * NN * NN, g_adj_lo + (size_t)b * NN * NN,
        g_w_hi, g_w_lo };

    if (tid < 128) sbias[tid] = bias[j0 + tid];

    uint32_t smb = smem_u32(sm);

    // prologue: stages 0..GSTAGES-2
    LOAD_CHUNK(0, 0);
    LOAD_CHUNK(1, 1);

    int warp_m = (wid & 1) * 64;
    int warp_j = (wid >> 1) * 32;
    int lrow   = lane & 15;
    int lhalf  = lane >> 4;

    float acc[4][4][4];
#pragma unroll
    for (int mt = 0; mt < 4; mt++)
#pragma unroll
        for (int jt = 0; jt < 4; jt++)
#pragma unroll
            for (int q = 0; q < 4; q++) acc[mt][jt][q] = 0.f;

    for (int c = 0; c < GCHUNKS; c++) {
        if (c + GSTAGES - 1 < GCHUNKS)
            LOAD_CHUNK(c + GSTAGES - 1, (c + GSTAGES - 1) % GSTAGES);
        CP_WAIT(GSTAGES - 1);
        __syncthreads();

        uint32_t sbase = smb + (c % GSTAGES) * STAGE_B;
#pragma unroll
        for (int k16 = 0; k16 < 2; k16++) {
            int chunkid = k16 * 2 + lhalf;
            uint32_t bf[2][2][4];   // [part][jt2][reg]
#pragma unroll
            for (int part = 0; part < 2; part++)
#pragma unroll
                for (int jt2 = 0; jt2 < 2; jt2++) {
                    int row = warp_j + jt2 * 16 + lrow;
                    uint32_t addr = sbase + (2 + part) * TILE_B + row * 64 +
                                    ((chunkid ^ ((row >> 1) & 3)) << 4);
                    LDM4(bf[part][jt2], addr);
                }
#pragma unroll
            for (int mt = 0; mt < 4; mt++) {
                int row = warp_m + mt * 16 + lrow;
                uint32_t off = row * 64 + ((chunkid ^ ((row >> 1) & 3)) << 4);
                uint32_t ah[4], al[4];
                LDM4(ah, sbase + off);
                LDM4(al, sbase + TILE_B + off);
#pragma unroll
                for (int jt = 0; jt < 4; jt++) {
                    int g = jt >> 1, o = jt & 1;
                    MMA16816(acc[mt][jt], ah, bf[0][g][o], bf[0][g][o + 2]);
                    MMA16816(acc[mt][jt], ah, bf[1][g][o], bf[1][g][o + 2]);
                    MMA16816(acc[mt][jt], al, bf[0][g][o], bf[0][g][o + 2]);
                }
            }
        }
        __syncthreads();
    }

    CP_WAIT(0);
    __syncthreads();

    // epilogue: signs -> smem byte tile -> packed maskT + degrees
    unsigned char* sgn = (unsigned char*)sm;   // [128 n][128 j]
#pragma unroll
    for (int mt = 0; mt < 4; mt++)
#pragma unroll
        for (int jt = 0; jt < 4; jt++) {
            int r0 = warp_m + mt * 16 + (lane >> 2);
            int jc = warp_j + jt * 8 + (lane & 3) * 2;
            float z00 = acc[mt][jt][0] + sbias[jc];
            float z01 = acc[mt][jt][1] + sbias[jc + 1];
            float z10 = acc[mt][jt][2] + sbias[jc];
            float z11 = acc[mt][jt][3] + sbias[jc + 1];
            sgn[r0 * 128 + jc]           = (z00 > 0.f) ? 1 : 0;
            sgn[r0 * 128 + jc + 1]       = (z01 > 0.f) ? 1 : 0;
            sgn[(r0 + 8) * 128 + jc]     = (z10 > 0.f) ? 1 : 0;
            sgn[(r0 + 8) * 128 + jc + 1] = (z11 > 0.f) ? 1 : 0;
        }
    __syncthreads();

    for (int idx = tid; idx < 512; idx += 256) {
        int jl = idx >> 2;
        int w  = idx & 3;
        unsigned word = 0;
#pragma unroll
        for (int i = 0; i < 32; i++)
            word |= ((unsigned)sgn[(w * 32 + i) * 128 + jl]) << i;
        g_maskT[((size_t)b * NN + j0 + jl) * NWORDS + (n0 >> 5) + w] = word;
    }
    if (tid < 128) {
        int s = 0;
#pragma unroll 16
        for (int j = 0; j < 128; j++) s += sgn[tid * 128 + j];
        atomicAdd(&g_deg[b * NN + n0 + tid], s);
    }
}

// ---------------- inv_sqrt_deg ----------------
__global__ void isd_kernel() {
    int i = blockIdx.x * blockDim.x + threadIdx.x;
    if (i < BATCH * NN) {
        int d = g_deg[i];
        g_isd[i] = (d > 0) ? (1.0f / sqrtf((float)d)) : 0.0f;
    }
}

// ---------------- one walk step ----------------
// 512 threads = 16 warps, 4 rows/warp -> 64 rows/block, SBLK=32 blocks/batch.
__global__ void __launch_bounds__(512) step_kernel(
    const float* __restrict__ coin, int step, float lf) {
    __shared__ float4 amp[NN];       // 32 KB
    __shared__ float  warpsum[16];

    int b    = blockIdx.y;
    int tid  = threadIdx.x;
    int lane = tid & 31;
    int wid  = tid >> 5;

    const float4* s_in  = (const float4*)((step & 1) ? g_sB : g_sA);
    float4*       s_out = (float4*)((step & 1) ? g_sA : g_sB);

    float d = 1.0f;
    if (step > 0) {
        const float* p = g_partials[(step - 1) & 1][b];
        float t = 0.f;
#pragma unroll
        for (int i = 0; i < SBLK; i++) t += p[i];
        d = sqrtf(t) + 1e-8f;
    }

    float c[8];
    float cn = 0.f;
#pragma unroll
    for (int i = 0; i < 8; i++) { c[i] = coin[i]; cn += c[i] * c[i]; }
    float inv = 1.0f / (sqrtf(cn) * d);
#pragma unroll
    for (int i = 0; i < 8; i++) c[i] *= inv;

    for (int n = tid; n < NN; n += 512) {
        float4 s = s_in[b * NN + n];
        float e0r = c[0] * s.x - c[1] * s.y + c[2] * s.z - c[3] * s.w;
        float e0i = c[0] * s.y + c[1] * s.x + c[2] * s.w + c[3] * s.z;
        float e1r = c[4] * s.x - c[5] * s.y + c[6] * s.z - c[7] * s.w;
        float e1i = c[4] * s.y + c[5] * s.x + c[6] * s.w + c[7] * s.z;
        float f = g_isd[b * NN + n];
        amp[n] = make_float4(e0r * f, e0i * f, e1r * f, e1i * f);
    }

    int m0 = blockIdx.x * 64 + wid * 4;
    unsigned mw[2][4];
#pragma unroll
    for (int r = 0; r < 4; r++) {
        const unsigned* basep = &g_maskT[((size_t)b * NN + m0 + r) * NWORDS];
        mw[0][r] = basep[lane];
        mw[1][r] = basep[32 + lane];
    }
    __syncthreads();

    unsigned long long a0[4], a1[4];
#pragma unroll
    for (int r = 0; r < 4; r++) { a0[r] = 0ull; a1[r] = 0ull; }
    unsigned lanebit = 1u << lane;

#pragma unroll
    for (int h = 0; h < 2; h++) {
#pragma unroll 8
        for (int w2 = 0; w2 < 32; w2++) {
            int n = ((h << 5) + w2) * 32 + lane;
            ulonglong2 v = *reinterpret_cast<const ulonglong2*>(&amp[n]);
#pragma unroll
            for (int r = 0; r < 4; r++) {
                unsigned word = __shfl_sync(0xffffffffu, mw[h][r], w2);
                unsigned bit = word & lanebit;
                asm volatile(
                    "{\n\t.reg .pred p;\n\t"
                    "setp.ne.u32 p, %4, 0;\n\t"
                    "@p add.rn.f32x2 %0, %0, %2;\n\t"
                    "@p add.rn.f32x2 %1, %1, %3;\n\t}"
                    : "+l"(a0[r]), "+l"(a1[r])
                    : "l"(v.x), "l"(v.y), "r"(bit));
            }
        }
    }

    float local = 0.f;
#pragma unroll
    for (int r = 0; r < 4; r++) {
        float ax = __uint_as_float((unsigned)a0[r]);
        float ay = __uint_as_float((unsigned)(a0[r] >> 32));
        float az = __uint_as_float((unsigned)a1[r]);
        float aw = __uint_as_float((unsigned)(a1[r] >> 32));
#pragma unroll
        for (int off = 16; off > 0; off >>= 1) {
            ax += __shfl_xor_sync(0xffffffffu, ax, off);
            ay += __shfl_xor_sync(0xffffffffu, ay, off);
            az += __shfl_xor_sync(0xffffffffu, az, off);
            aw += __shfl_xor_sync(0xffffffffu, aw, off);
        }
        if (lane == 0) {
            int m = m0 + r;
            if (g_deg[b * NN + m] == 0) {
                float4 s = s_in[b * NN + m];
                ax = c[0] * s.x - c[1] * s.y + c[2] * s.z - c[3] * s.w;
                ay = c[0] * s.y + c[1] * s.x + c[2] * s.w + c[3] * s.z;
                az = c[4] * s.x - c[5] * s.y + c[6] * s.z - c[7] * s.w;
                aw = c[4] * s.y + c[5] * s.x + c[6] * s.w + c[7] * s.z;
            }
            ax *= lf; ay *= lf; az *= lf; aw *= lf;
            s_out[b * NN + m] = make_float4(ax, ay, az, aw);
            local += ax * ax + ay * ay + az * az + aw * aw;
        }
    }
    if (lane == 0) warpsum[wid] = local;
    __syncthreads();
    if (tid == 0) {
        float t = 0.f;
#pragma unroll
        for (int i = 0; i < 16; i++) t += warpsum[i];
        g_partials[step & 1][b][blockIdx.x] = t;
    }
}

// ---------------- final probs + 2-layer MLP ----------------
__global__ void __launch_bounds__(128) fc_kernel(
    const float* __restrict__ f1w, const float* __restrict__ f1b,
    const float* __restrict__ f2w, const float* __restrict__ f2b,
    float* __restrict__ out) {
    __shared__ __align__(16) float probs[NN * 2];
    __shared__ float h[128];
    int b = blockIdx.x, tid = threadIdx.x;

    const float* p = g_partials[(STEPS - 1) & 1][b];
    float t = 0.f;
#pragma unroll
    for (int i = 0; i < SBLK; i++) t += p[i];
    float dd = sqrtf(t) + 1e-8f;
    float sc = 1.0f / (dd * dd);

    const float4* s = (const float4*)g_sA;
    for (int n = tid; n < NN; n += 128) {
        float4 v = s[b * NN + n];
        probs[2 * n]     = (v.x * v.x + v.y * v.y) * sc;
        probs[2 * n + 1] = (v.z * v.z + v.w * v.w) * sc;
    }
    __syncthreads();

    {
        int j = tid;
        float acc = f1b[j];
        const float4* w4 = (const float4*)(f1w + (size_t)j * NN * 2);
        const float4* p4 = (const float4*)probs;
#pragma unroll 4
        for (int i = 0; i < NN * 2 / 4; i++) {
            float4 w = w4[i];
            float4 q = p4[i];
            acc += w.x * q.x + w.y * q.y + w.z * q.z + w.w * q.w;
        }
        h[j] = fmaxf(acc, 0.f);
    }
    __syncthreads();
    if (tid < 64) {
        float acc = f2b[tid];
#pragma unroll 8
        for (int j = 0; j < 128; j++) acc += h[j] * f2w[tid * 128 + j];
        out[b * 64 + tid] = acc;
    }
}

// ---------------- launch ----------------
extern "C" void kernel_launch(void* const* d_in, const int* in_sizes, int n_in,
                              void* d_out, int out_size) {
    const float* adj  = (const float*)d_in[0];
    const float* coin = (const float*)d_in[1];
    const float* encw = (const float*)d_in[2];
    const float* encb = (const float*)d_in[3];
    const float* f1w  = (const float*)d_in[4];
    const float* f1b  = (const float*)d_in[5];
    const float* f2w  = (const float*)d_in[6];
    const float* f2b  = (const float*)d_in[7];
    float* out = (float*)d_out;

    cudaFuncSetAttribute(gemm_mask_mma,
                         cudaFuncAttributeMaxDynamicSharedMemorySize,
                         GSTAGES * STAGE_B);

    init_kernel<<<(BATCH * NN * 4 + 255) / 256, 256>>>();

    {   // bf16 hi/lo splits
        __nv_bfloat16 *ahi, *alo, *whi, *wlo;
        cudaGetSymbolAddress((void**)&ahi, g_adj_hi);
        cudaGetSymbolAddress((void**)&alo, g_adj_lo);
        cudaGetSymbolAddress((void**)&whi, g_w_hi);
        cudaGetSymbolAddress((void**)&wlo, g_w_lo);
        size_t n4a = (size_t)BATCH * NN * NN / 4;
        size_t n4w = (size_t)NN * NN / 4;
        conv_split_kernel<<<(unsigned)((n4a + 255) / 256), 256>>>(adj, ahi, alo, n4a);
        conv_split_kernel<<<(unsigned)((n4w + 255) / 256), 256>>>(encw, whi, wlo, n4w);
    }

    gemm_mask_mma<<<dim3(NN / 128, NN / 128, BATCH), 256, GSTAGES * STAGE_B>>>(encb);

    isd_kernel<<<(BATCH * NN + 255) / 256, 256>>>();

    for (int t = 0; t < STEPS; t++) {
        step_kernel<<<dim3(SBLK, BATCH), 512>>>(coin, t, expf(-0.01f * (float)t));
    }

    fc_kernel<<<BATCH, 128>>>(f1w, f1b, f2w, f2b, out);
}